// round 12
// baseline (speedup 1.0000x reference)
#include <cuda_runtime.h>
#include <cuda_fp16.h>
#include <cstdint>

#define NT 131072
#define NCODE 1024
#define TOKB 64
#define NBLK (NT / TOKB)
#define QCAP 768

__device__ float  g_esq[NCODE];
__device__ float  g_emaxb[128];
__device__ int    g_s8b[64];
__device__ int    g_hist[NCODE];
__device__ double g_partial[NBLK];
__device__ unsigned g_done;
__device__ unsigned g_cbq[NCODE * 16];   // s8-packed codebook rows (64 B/code)

// ---- smem byte offsets ----
#define O_ZA   0        // s8 [64][80]              5120
#define O_B    5120     // s8 [2][256][80]          40960
#define O_SC0  46080    // half[64][264]            33792  (chunk-0 scores)
#define O_EQ   79872    // float[1024]
#define O_ZQ   83968    // float[64]
#define O_DL   84224    // float[64]
#define O_SF   84480    // float[64]
#define O_ISZ  84736    // float[64]
#define O_MN   84992    // uint [64]
#define O_CD   85248    // u64  [64]
#define O_QU   85760    // u32  [768]
#define O_QC   88832    // u32 x2
#define O_P    88840    // float[3][256]
#define O_RD   91912    // double[256]
#define SMEMSZ 93960

static __device__ __forceinline__ void imma(int* c, const unsigned* a, const unsigned* b) {
    asm volatile("mma.sync.aligned.m16n8k32.row.col.s32.s8.s8.s32 "
        "{%0,%1,%2,%3},{%4,%5,%6,%7},{%8,%9},{%0,%1,%2,%3};"
        : "+r"(c[0]), "+r"(c[1]), "+r"(c[2]), "+r"(c[3])
        : "r"(a[0]), "r"(a[1]), "r"(a[2]), "r"(a[3]), "r"(b[0]), "r"(b[1]));
}
static __device__ __forceinline__ unsigned long long packkey(float s, int k) {
    unsigned u = __float_as_uint(s);
    u = ((int)u < 0) ? ~u : (u | 0x80000000u);
    return ((unsigned long long)u << 32) | (unsigned)k;
}
static __device__ __forceinline__ unsigned fmap(float s) {
    unsigned u = __float_as_uint(s);
    return ((int)u < 0) ? ~u : (u | 0x80000000u);
}
static __device__ __forceinline__ float unmap(unsigned u) {
    return __uint_as_float((u & 0x80000000u) ? (u & 0x7FFFFFFFu) : ~u);
}
static __device__ __forceinline__ float exact_score(const float4* zr, const float4* cr,
                                                    float zsq, float esq) {
    float dot = 0.f;
    #pragma unroll
    for (int m = 0; m < 16; ++m) {
        float4 a = zr[m], b = cr[m];
        dot = fmaf(a.x, b.x, dot); dot = fmaf(a.y, b.y, dot);
        dot = fmaf(a.z, b.z, dot); dot = fmaf(a.w, b.w, dot);
    }
    return fmaf(-2.f, dot, zsq) + esq;
}

// ---------------- prep1 ----------------
__global__ void __launch_bounds__(256) vq_prep(const float* __restrict__ cb)
{
    __shared__ float wm[8];
    int w = threadIdx.x >> 5, l = threadIdx.x & 31;
    int k = blockIdx.x * 8 + w;
    float2 v = ((const float2*)(cb + (size_t)k * 64))[l];
    float sq = fmaf(v.y, v.y, v.x * v.x);
    float am = fmaxf(fabsf(v.x), fabsf(v.y));
    #pragma unroll
    for (int o = 16; o; o >>= 1) {
        sq += __shfl_xor_sync(~0u, sq, o);
        am = fmaxf(am, __shfl_xor_sync(~0u, am, o));
    }
    if (l == 0) { g_esq[k] = sq; wm[w] = am; }
    __syncthreads();
    if (threadIdx.x == 0) {
        float m = wm[0];
        #pragma unroll
        for (int i = 1; i < 8; ++i) m = fmaxf(m, wm[i]);
        g_emaxb[blockIdx.x] = m;
    }
    if (threadIdx.x < 8) g_hist[blockIdx.x * 8 + threadIdx.x] = 0;
}

// ---------------- prep2 ----------------
__global__ void __launch_bounds__(256) vq_quant(const float* __restrict__ cb)
{
    __shared__ float sm[128];
    __shared__ int scode[16];
    int tid = threadIdx.x;
    if (tid < 128) sm[tid] = g_emaxb[tid];
    __syncthreads();
    if (tid == 0) {
        float m = sm[0];
        for (int i = 1; i < 128; ++i) m = fmaxf(m, sm[i]);
        sm[0] = m;
    }
    __syncthreads();
    float inv_se = 127.f / sm[0];
    int code = blockIdx.x * 16 + (tid >> 4), q = tid & 15;
    float4 v = *(const float4*)(cb + (size_t)code * 64 + q * 4);
    int a = __float2int_rn(v.x * inv_se), b = __float2int_rn(v.y * inv_se);
    int c = __float2int_rn(v.z * inv_se), d = __float2int_rn(v.w * inv_se);
    g_cbq[code * 16 + q] = (a & 255) | ((b & 255) << 8) | ((c & 255) << 16) | ((d & 255) << 24);
    int s = abs(a) + abs(b) + abs(c) + abs(d);
    #pragma unroll
    for (int o = 8; o; o >>= 1) s += __shfl_down_sync(~0u, s, o, 16);
    if (q == 0) scode[tid >> 4] = s;
    __syncthreads();
    if (tid == 0) {
        int m = scode[0];
        #pragma unroll
        for (int i = 1; i < 16; ++i) m = max(m, scode[i]);
        g_s8b[blockIdx.x] = m;
    }
}

// ---------------- main ----------------
extern __shared__ unsigned char smraw[];

__global__ void __launch_bounds__(256, 2)
vq_main(const float* __restrict__ z, const float* __restrict__ cb, float* __restrict__ out)
{
    signed char* sZA = (signed char*)(smraw + O_ZA);
    signed char* sB = (signed char*)(smraw + O_B);
    __half* sbuf = (__half*)(smraw + O_SC0);
    float* seq  = (float*)(smraw + O_EQ);
    float* szq  = (float*)(smraw + O_ZQ);
    float* sdl  = (float*)(smraw + O_DL);
    float* ssf  = (float*)(smraw + O_SF);
    float* sisz = (float*)(smraw + O_ISZ);
    unsigned* smn = (unsigned*)(smraw + O_MN);
    unsigned long long* cand = (unsigned long long*)(smraw + O_CD);
    unsigned* qu = (unsigned*)(smraw + O_QU);
    unsigned* qc = (unsigned*)(smraw + O_QC);
    float* psq = (float*)(smraw + O_P);
    float* pab = psq + 256;
    float* pmx = psq + 512;
    double* srd = (double*)(smraw + O_RD);

    const int tid = threadIdx.x, w = tid >> 5, l = tid & 31;
    const int tb = blockIdx.x * TOKB;
    const int gr = l >> 2, tig = l & 3;
    const unsigned sBsh = (unsigned)__cvta_generic_to_shared(sB);
    const char* cbq = (const char*)g_cbq;

    #pragma unroll
    for (int cc = 0; cc < 2; ++cc) {
        for (int i = tid; i < 1024; i += 256) {
            int code = i >> 2, seg = i & 3;
            asm volatile("cp.async.cg.shared.global [%0], [%1], 16;"
                :: "r"(sBsh + cc * 20480 + code * 80 + seg * 16),
                   "l"(cbq + (size_t)(cc * 256 + code) * 64 + seg * 16));
        }
        asm volatile("cp.async.commit_group;");
    }

    const int t = tid >> 2, q = tid & 3;
    {
        const float4* zp = (const float4*)(z + (size_t)(tb + t) * 64 + q * 16);
        float ps = 0.f, pa = 0.f, pm = 0.f;
        #pragma unroll
        for (int j = 0; j < 4; ++j) {
            float4 v = zp[j];
            ps = fmaf(v.x, v.x, ps); ps = fmaf(v.y, v.y, ps);
            ps = fmaf(v.z, v.z, ps); ps = fmaf(v.w, v.w, ps);
            pa += fabsf(v.x) + fabsf(v.y) + fabsf(v.z) + fabsf(v.w);
            pm = fmaxf(pm, fmaxf(fmaxf(fabsf(v.x), fabsf(v.y)), fmaxf(fabsf(v.z), fabsf(v.w))));
        }
        psq[tid] = ps; pab[tid] = pa; pmx[tid] = pm;
    }
    if (tid < 128) ((float*)qu)[tid] = g_emaxb[tid];
    if (tid < 64) { ((int*)qu)[128 + tid] = g_s8b[tid]; smn[tid] = 0xFFFFFFFFu; cand[tid] = ~0ULL; }
    if (tid == 0) { qc[0] = 0; qc[1] = 0; }
    for (int i = tid; i < NCODE; i += 256) seq[i] = g_esq[i];
    __syncthreads();

    if (tid < 64) {
        float em = ((float*)qu)[0];
        #pragma unroll
        for (int i = 1; i < 128; ++i) em = fmaxf(em, ((float*)qu)[i]);
        int S8 = ((int*)qu)[128];
        #pragma unroll
        for (int i = 1; i < 64; ++i) S8 = max(S8, ((int*)qu)[128 + i]);
        float zq_ = psq[tid * 4] + psq[tid * 4 + 1] + psq[tid * 4 + 2] + psq[tid * 4 + 3];
        float ab  = pab[tid * 4] + pab[tid * 4 + 1] + pab[tid * 4 + 2] + pab[tid * 4 + 3];
        float mx  = fmaxf(fmaxf(pmx[tid * 4], pmx[tid * 4 + 1]), fmaxf(pmx[tid * 4 + 2], pmx[tid * 4 + 3]));
        float se = em * (1.f / 127.f);
        float zm = fmaxf(mx, 1e-30f);
        float sz = zm * (1.f / 127.f);
        szq[tid] = zq_;
        ssf[tid] = -2.f * se * sz;
        sdl[tid] = se * (ab + sz * (float)S8) + 1e-4f;
        sisz[tid] = 127.f / zm;
    }
    __syncthreads();

    {   // quantize z into smem s8 (stride 80)
        float isz = sisz[t];
        const float4* zp = (const float4*)(z + (size_t)(tb + t) * 64 + q * 16);
        #pragma unroll
        for (int j = 0; j < 4; ++j) {
            float4 v = zp[j];
            int a = __float2int_rn(v.x * isz), b = __float2int_rn(v.y * isz);
            int c = __float2int_rn(v.z * isz), d = __float2int_rn(v.w * isz);
            *(unsigned*)(sZA + t * 80 + q * 16 + j * 4) =
                (a & 255) | ((b & 255) << 8) | ((c & 255) << 16) | ((d & 255) << 24);
        }
    }
    asm volatile("cp.async.wait_group 1;");
    __syncthreads();

    // IMMA A fragments (all 64 tokens)
    unsigned Ar[4][2][4];
    #pragma unroll
    for (int m = 0; m < 4; ++m)
        #pragma unroll
        for (int kh = 0; kh < 2; ++kh) {
            int base = (m * 16 + gr) * 80 + tig * 4 + kh * 32;
            Ar[m][kh][0] = *(const unsigned*)(sZA + base);
            Ar[m][kh][1] = *(const unsigned*)(sZA + base + 640);
            Ar[m][kh][2] = *(const unsigned*)(sZA + base + 16);
            Ar[m][kh][3] = *(const unsigned*)(sZA + base + 656);
        }
    float sf2[4][2];
    #pragma unroll
    for (int m = 0; m < 4; ++m) {
        sf2[m][0] = ssf[m * 16 + gr];
        sf2[m][1] = ssf[m * 16 + gr + 8];
    }
    float minv[8], thrv[8];
    #pragma unroll
    for (int i = 0; i < 8; ++i) { minv[i] = 3.4e38f; thrv[i] = 0.f; }

    // dp4a lane mapping: 8 tokens (tg*8+i), 2 codes (w*32+24+cl+s)
    const int tg = l >> 2, cl = (l & 3) * 2;

    // hybrid pass over one 256-code chunk: j=0..2 IMMA (24 codes/warp) + dp4a (8 codes/warp)
    auto pass = [&](const signed char* bb, int cb0, bool enq, bool store) {
        // ---- dp4a part (interleaves with IMMA on separate pipe if HW allows) ----
        float dmin[8];
        #pragma unroll
        for (int i = 0; i < 8; ++i) dmin[i] = 3.4e38f;
        float thr8[8];
        if (enq) {
            #pragma unroll
            for (int i = 0; i < 8; ++i) {
                int tok = tg * 8 + i;
                thr8[i] = unmap(smn[tok]) + sdl[tok];
            }
        }
        #pragma unroll
        for (int s = 0; s < 2; ++s) {
            int cloc = w * 32 + 24 + cl + s;
            const uint4* ep4 = (const uint4*)(bb + cloc * 80);
            uint4 e0 = ep4[0], e1 = ep4[1], e2 = ep4[2], e3 = ep4[3];
            float eq = seq[cb0 + cloc];
            #pragma unroll
            for (int i = 0; i < 8; ++i) {
                int tok = tg * 8 + i;
                const uint4* zp4 = (const uint4*)(sZA + tok * 80);
                uint4 z0 = zp4[0], z1 = zp4[1], z2 = zp4[2], z3 = zp4[3];
                int a = 0;
                a = __dp4a((int)z0.x,(int)e0.x,a); a = __dp4a((int)z0.y,(int)e0.y,a);
                a = __dp4a((int)z0.z,(int)e0.z,a); a = __dp4a((int)z0.w,(int)e0.w,a);
                a = __dp4a((int)z1.x,(int)e1.x,a); a = __dp4a((int)z1.y,(int)e1.y,a);
                a = __dp4a((int)z1.z,(int)e1.z,a); a = __dp4a((int)z1.w,(int)e1.w,a);
                a = __dp4a((int)z2.x,(int)e2.x,a); a = __dp4a((int)z2.y,(int)e2.y,a);
                a = __dp4a((int)z2.z,(int)e2.z,a); a = __dp4a((int)z2.w,(int)e2.w,a);
                a = __dp4a((int)z3.x,(int)e3.x,a); a = __dp4a((int)z3.y,(int)e3.y,a);
                a = __dp4a((int)z3.z,(int)e3.z,a); a = __dp4a((int)z3.w,(int)e3.w,a);
                float sc = fmaf(ssf[tok], (float)a, eq);
                dmin[i] = fminf(dmin[i], sc);
                if (store) sbuf[tok * 264 + cloc] = __float2half_rn(sc);
                if (enq && sc <= thr8[i]) {
                    unsigned p = atomicAdd(qc, 1u);
                    if (p < QCAP) qu[p] = ((unsigned)tok << 16) | (unsigned)(cb0 + cloc);
                    else qc[1] = 1;
                }
            }
        }
        // ---- IMMA part: j = 0..2 ----
        #pragma unroll
        for (int j = 0; j < 3; ++j) {
            int crow = (w * 32 + j * 8 + gr) * 80 + tig * 4;
            unsigned B0[2], B1[2];
            B0[0] = *(const unsigned*)(bb + crow);
            B0[1] = *(const unsigned*)(bb + crow + 16);
            B1[0] = *(const unsigned*)(bb + crow + 32);
            B1[1] = *(const unsigned*)(bb + crow + 48);
            int col = cb0 + w * 32 + j * 8 + tig * 2;
            float eqA = seq[col], eqB = seq[col + 1];
            int C[4][4];
            #pragma unroll
            for (int m = 0; m < 4; ++m) { C[m][0] = 0; C[m][1] = 0; C[m][2] = 0; C[m][3] = 0; }
            #pragma unroll
            for (int m = 0; m < 4; ++m) imma(C[m], Ar[m][0], B0);
            #pragma unroll
            for (int m = 0; m < 4; ++m) imma(C[m], Ar[m][1], B1);
            #pragma unroll
            for (int m = 0; m < 4; ++m) {
                float s0 = fmaf(sf2[m][0], (float)C[m][0], eqA);
                float s1 = fmaf(sf2[m][0], (float)C[m][1], eqB);
                float s2 = fmaf(sf2[m][1], (float)C[m][2], eqA);
                float s3 = fmaf(sf2[m][1], (float)C[m][3], eqB);
                minv[2 * m]     = fminf(minv[2 * m], fminf(s0, s1));
                minv[2 * m + 1] = fminf(minv[2 * m + 1], fminf(s2, s3));
                int tlo = m * 16 + gr, thi = tlo + 8;
                if (store) {
                    int lc = col - cb0;
                    *(__half2*)(sbuf + tlo * 264 + lc) = __floats2half2_rn(s0, s1);
                    *(__half2*)(sbuf + thi * 264 + lc) = __floats2half2_rn(s2, s3);
                }
                if (enq) {
                    if (s0 <= thrv[2 * m]) {
                        unsigned p = atomicAdd(qc, 1u);
                        if (p < QCAP) qu[p] = ((unsigned)tlo << 16) | (unsigned)col; else qc[1] = 1;
                    }
                    if (s1 <= thrv[2 * m]) {
                        unsigned p = atomicAdd(qc, 1u);
                        if (p < QCAP) qu[p] = ((unsigned)tlo << 16) | (unsigned)(col + 1); else qc[1] = 1;
                    }
                    if (s2 <= thrv[2 * m + 1]) {
                        unsigned p = atomicAdd(qc, 1u);
                        if (p < QCAP) qu[p] = ((unsigned)thi << 16) | (unsigned)col; else qc[1] = 1;
                    }
                    if (s3 <= thrv[2 * m + 1]) {
                        unsigned p = atomicAdd(qc, 1u);
                        if (p < QCAP) qu[p] = ((unsigned)thi << 16) | (unsigned)(col + 1); else qc[1] = 1;
                    }
                }
            }
        }
        // dp4a min reduce: over the 4 code-lanes (xor 1, 2)
        #pragma unroll
        for (int i = 0; i < 8; ++i) {
            float m = dmin[i];
            m = fminf(m, __shfl_xor_sync(~0u, m, 1));
            m = fminf(m, __shfl_xor_sync(~0u, m, 2));
            if ((l & 3) == 0) atomicMin(&smn[tg * 8 + i], fmap(m));
        }
    };
    auto minred = [&]() {
        #pragma unroll
        for (int i = 0; i < 8; ++i) {
            float m = minv[i];
            m = fminf(m, __shfl_xor_sync(~0u, m, 1));
            m = fminf(m, __shfl_xor_sync(~0u, m, 2));
            if (tig == 0) {
                int tt = (i >> 1) * 16 + gr + (i & 1) * 8;
                atomicMin(&smn[tt], fmap(m));
            }
        }
    };
    auto loadthr = [&]() {
        #pragma unroll
        for (int i = 0; i < 8; ++i) {
            int tt = (i >> 1) * 16 + gr + (i & 1) * 8;
            thrv[i] = unmap(smn[tt]) + sdl[tt];
        }
    };

    // pre-pass: chunk 0, store scores + min
    pass(sB, 0, false, true);
    minred();
    __syncthreads();

    // chunk-0 slot free -> prefetch chunk 2 into slot 0
    for (int i = tid; i < 1024; i += 256) {
        int code = i >> 2, seg = i & 3;
        asm volatile("cp.async.cg.shared.global [%0], [%1], 16;"
            :: "r"(sBsh + code * 80 + seg * 16),
               "l"(cbq + (size_t)(512 + code) * 64 + seg * 16));
    }
    asm volatile("cp.async.commit_group;");

    // chunk-0 candidate scan from buffer
    #pragma unroll 1
    for (int r = 0; r < 8; ++r) {
        int tt = w * 8 + r;
        float thr = unmap(smn[tt]) + sdl[tt];
        uint4 v = *(const uint4*)(sbuf + tt * 264 + l * 8);
        const __half* h = (const __half*)&v;
        #pragma unroll
        for (int p = 0; p < 8; ++p)
            if (__half2float(h[p]) <= thr) {
                unsigned pos = atomicAdd(qc, 1u);
                if (pos < QCAP) qu[pos] = ((unsigned)tt << 16) | (unsigned)(l * 8 + p); else qc[1] = 1;
            }
    }

    // main chunks 1..3
    #pragma unroll 1
    for (int c = 1; c <= 3; ++c) {
        if (c < 3) asm volatile("cp.async.wait_group 1;");
        else       asm volatile("cp.async.wait_group 0;");
        __syncthreads();
        loadthr();
        pass(sB + (c & 1) * 20480, c * 256, true, false);
        if (c < 3) {
            minred();
            __syncthreads();
            if (c == 1) {
                for (int i = tid; i < 1024; i += 256) {
                    int code = i >> 2, seg = i & 3;
                    asm volatile("cp.async.cg.shared.global [%0], [%1], 16;"
                        :: "r"(sBsh + 20480 + code * 80 + seg * 16),
                           "l"(cbq + (size_t)(768 + code) * 64 + seg * 16));
                }
                asm volatile("cp.async.commit_group;");
            }
        }
    }
    __syncthreads();

    // exact rescore of candidates
    if (!qc[1]) {
        unsigned n = min(qc[0], (unsigned)QCAP);
        for (unsigned i = tid; i < n; i += 256) {
            unsigned e = qu[i];
            int tt = (int)(e >> 16), k = (int)(e & 0xffffu);
            float s = exact_score((const float4*)(z + (size_t)(tb + tt) * 64),
                                  (const float4*)(cb + (size_t)k * 64), szq[tt], seq[k]);
            atomicMin(&cand[tt], packkey(s, k));
        }
    } else {
        int tt = tid >> 2, kb = (tid & 3) * 256;
        unsigned long long best = ~0ULL;
        for (int k = kb; k < kb + 256; ++k) {
            float s = exact_score((const float4*)(z + (size_t)(tb + tt) * 64),
                                  (const float4*)(cb + (size_t)k * 64), szq[tt], seq[k]);
            unsigned long long p = packkey(s, k);
            if (p < best) best = p;
        }
        atomicMin(&cand[tt], best);
    }
    __syncthreads();

    // outputs: index, STE, MSE partial, hist
    {
        int idx = (int)(unsigned)cand[t];
        if (q == 0) {
            out[(size_t)NT * 64 + tb + t] = (float)idx;
            atomicAdd(&g_hist[idx], 1);
        }
        const float4* cp = (const float4*)(cb + (size_t)idx * 64 + q * 16);
        const float4* zp = (const float4*)(z + (size_t)(tb + t) * 64 + q * 16);
        float* op = out + (size_t)(tb + t) * 64 + q * 16;
        double acc = 0.0;
        #pragma unroll
        for (int j = 0; j < 4; ++j) {
            float4 e = cp[j], v = zp[j];
            float dx = e.x - v.x, dy = e.y - v.y, dz = e.z - v.z, dw = e.w - v.w;
            *(float4*)(op + j * 4) = make_float4(v.x + dx, v.y + dy, v.z + dz, v.w + dw);
            acc += (double)(dx * dx) + (double)(dy * dy) + (double)(dz * dz) + (double)(dw * dw);
        }
        srd[tid] = acc;
    }
    __syncthreads();
    #pragma unroll
    for (int o = 128; o; o >>= 1) {
        if (tid < o) srd[tid] += srd[tid + o];
        __syncthreads();
    }
    if (tid == 0) g_partial[blockIdx.x] = srd[0];

    // ---- fused finalization ----
    __threadfence();
    __shared__ unsigned lastblk;
    if (tid == 0) lastblk = (atomicAdd(&g_done, 1u) == (unsigned)(NBLK - 1)) ? 1u : 0u;
    __syncthreads();
    if (!lastblk) return;

    double acc = 0.0;
    for (int i = tid; i < NBLK; i += 256) acc += g_partial[i];
    srd[tid] = acc;
    __syncthreads();
    #pragma unroll
    for (int o = 128; o; o >>= 1) {
        if (tid < o) srd[tid] += srd[tid + o];
        __syncthreads();
    }
    double sl = srd[0];
    __syncthreads();

    double ent = 0.0;
    for (int i = tid; i < NCODE; i += 256) {
        float p = (float)g_hist[i] / 131072.0f + 1e-10f;
        ent += (double)(p * logf(p));
    }
    srd[tid] = ent;
    __syncthreads();
    #pragma unroll
    for (int o = 128; o; o >>= 1) {
        if (tid < o) srd[tid] += srd[tid + o];
        __syncthreads();
    }
    if (tid == 0) {
        const size_t b = (size_t)NT * 64 + NT;
        float cl = (float)(sl / (double)((size_t)NT * 64));
        float en = (float)(-srd[0]);
        out[b + 0] = cl;
        out[b + 1] = 0.25f * cl;
        out[b + 2] = -0.1f * (en / 6.9314718055994531f);
        out[b + 3] = expf(en);
        g_done = 0;
    }
}

extern "C" void kernel_launch(void* const* d_in, const int* in_sizes, int n_in,
                              void* d_out, int out_size)
{
    const float* z  = (const float*)d_in[0];
    const float* cb = (const float*)d_in[1];
    float* out = (float*)d_out;
    static bool done = false;
    if (!done) {
        cudaFuncSetAttribute(vq_main, cudaFuncAttributeMaxDynamicSharedMemorySize, SMEMSZ);
        done = true;
    }
    vq_prep<<<128, 256>>>(cb);
    vq_quant<<<64, 256>>>(cb);
    vq_main<<<NBLK, 256, SMEMSZ>>>(z, cb, out);
}

// round 14
// speedup vs baseline: 1.2988x; 1.2988x over previous
#include <cuda_runtime.h>
#include <cuda_fp16.h>
#include <cstdint>

#define NT 131072
#define NCODE 1024
#define TOKB 64
#define NBLK (NT / TOKB)
#define QCAP 768

__device__ float  g_esq[NCODE];
__device__ float  g_emaxb[128];
__device__ int    g_s8b[64];
__device__ int    g_hist[NCODE];
__device__ double g_partial[NBLK];
__device__ unsigned g_done;
__device__ unsigned g_cbq[NCODE * 16];   // s8-packed codebook rows (64 B/code)

// ---- smem byte offsets ----
#define O_A    0        // s8 [64][80]              5120
#define O_B    5120     // s8 [2][256][80]          40960
#define O_EQ   46080    // float[1024]              4096
#define O_ZQ   50176    // float[64]
#define O_DL   50432    // float[64]
#define O_SF   50688    // float[64]
#define O_ISZ  50944    // float[64]
#define O_MN   51200    // uint [64]
#define O_CD   51456    // u64  [64]
#define O_QU   51968    // u32  [768]
#define O_QC   55040    // u32 x2
#define O_P    55048    // float[3][256]
#define O_RD   58120    // double[256]
#define SMEMSZ 60168

static __device__ __forceinline__ void imma(int* c, const unsigned* a, const unsigned* b) {
    asm volatile("mma.sync.aligned.m16n8k32.row.col.s32.s8.s8.s32 "
        "{%0,%1,%2,%3},{%4,%5,%6,%7},{%8,%9},{%0,%1,%2,%3};"
        : "+r"(c[0]), "+r"(c[1]), "+r"(c[2]), "+r"(c[3])
        : "r"(a[0]), "r"(a[1]), "r"(a[2]), "r"(a[3]), "r"(b[0]), "r"(b[1]));
}
static __device__ __forceinline__ unsigned long long packkey(float s, int k) {
    unsigned u = __float_as_uint(s);
    u = ((int)u < 0) ? ~u : (u | 0x80000000u);
    return ((unsigned long long)u << 32) | (unsigned)k;
}
static __device__ __forceinline__ unsigned fmap(float s) {
    unsigned u = __float_as_uint(s);
    return ((int)u < 0) ? ~u : (u | 0x80000000u);
}
static __device__ __forceinline__ float unmap(unsigned u) {
    return __uint_as_float((u & 0x80000000u) ? (u & 0x7FFFFFFFu) : ~u);
}
static __device__ __forceinline__ float exact_score(const float4* zr, const float4* cr,
                                                    float zsq, float esq) {
    float dot = 0.f;
    #pragma unroll
    for (int m = 0; m < 16; ++m) {
        float4 a = zr[m], b = cr[m];
        dot = fmaf(a.x, b.x, dot); dot = fmaf(a.y, b.y, dot);
        dot = fmaf(a.z, b.z, dot); dot = fmaf(a.w, b.w, dot);
    }
    return fmaf(-2.f, dot, zsq) + esq;
}

// ---------------- prep1: esq, emax per block, zero hist ----------------
__global__ void __launch_bounds__(256) vq_prep(const float* __restrict__ cb)
{
    __shared__ float wm[8];
    int w = threadIdx.x >> 5, l = threadIdx.x & 31;
    int k = blockIdx.x * 8 + w;
    float2 v = ((const float2*)(cb + (size_t)k * 64))[l];
    float sq = fmaf(v.y, v.y, v.x * v.x);
    float am = fmaxf(fabsf(v.x), fabsf(v.y));
    #pragma unroll
    for (int o = 16; o; o >>= 1) {
        sq += __shfl_xor_sync(~0u, sq, o);
        am = fmaxf(am, __shfl_xor_sync(~0u, am, o));
    }
    if (l == 0) { g_esq[k] = sq; wm[w] = am; }
    __syncthreads();
    if (threadIdx.x == 0) {
        float m = wm[0];
        #pragma unroll
        for (int i = 1; i < 8; ++i) m = fmaxf(m, wm[i]);
        g_emaxb[blockIdx.x] = m;
    }
    if (threadIdx.x < 8) g_hist[blockIdx.x * 8 + threadIdx.x] = 0;
}

// ---------------- prep2: quantize codebook to s8, per-block S8 max ----------------
__global__ void __launch_bounds__(256) vq_quant(const float* __restrict__ cb)
{
    __shared__ float sm[128];
    __shared__ int scode[16];
    int tid = threadIdx.x;
    if (tid < 128) sm[tid] = g_emaxb[tid];
    __syncthreads();
    if (tid == 0) {
        float m = sm[0];
        for (int i = 1; i < 128; ++i) m = fmaxf(m, sm[i]);
        sm[0] = m;
    }
    __syncthreads();
    float inv_se = 127.f / sm[0];
    int code = blockIdx.x * 16 + (tid >> 4), q = tid & 15;
    float4 v = *(const float4*)(cb + (size_t)code * 64 + q * 4);
    int a = __float2int_rn(v.x * inv_se), b = __float2int_rn(v.y * inv_se);
    int c = __float2int_rn(v.z * inv_se), d = __float2int_rn(v.w * inv_se);
    g_cbq[code * 16 + q] = (a & 255) | ((b & 255) << 8) | ((c & 255) << 16) | ((d & 255) << 24);
    int s = abs(a) + abs(b) + abs(c) + abs(d);
    #pragma unroll
    for (int o = 8; o; o >>= 1) s += __shfl_down_sync(~0u, s, o, 16);
    if (q == 0) scode[tid >> 4] = s;
    __syncthreads();
    if (tid == 0) {
        int m = scode[0];
        #pragma unroll
        for (int i = 1; i < 16; ++i) m = max(m, scode[i]);
        g_s8b[blockIdx.x] = m;
    }
}

// ---------------- main (occ 3) ----------------
extern __shared__ unsigned char smraw[];

__global__ void __launch_bounds__(256, 3)
vq_main(const float* __restrict__ z, const float* __restrict__ cb, float* __restrict__ out)
{
    signed char* sA = (signed char*)(smraw + O_A);
    signed char* sB = (signed char*)(smraw + O_B);
    float* seq  = (float*)(smraw + O_EQ);
    float* szq  = (float*)(smraw + O_ZQ);
    float* sdl  = (float*)(smraw + O_DL);
    float* ssf  = (float*)(smraw + O_SF);
    float* sisz = (float*)(smraw + O_ISZ);
    unsigned* smn = (unsigned*)(smraw + O_MN);
    unsigned long long* cand = (unsigned long long*)(smraw + O_CD);
    unsigned* qu = (unsigned*)(smraw + O_QU);
    unsigned* qc = (unsigned*)(smraw + O_QC);
    float* psq = (float*)(smraw + O_P);
    float* pab = psq + 256;
    float* pmx = psq + 512;
    double* srd = (double*)(smraw + O_RD);

    const int tid = threadIdx.x, w = tid >> 5, l = tid & 31;
    const int tb = blockIdx.x * TOKB;
    const int gr = l >> 2, tig = l & 3;
    const unsigned sBsh = (unsigned)__cvta_generic_to_shared(sB);
    const char* cbq = (const char*)g_cbq;

    // prefetch B chunks 0,1 (s8, 64 B/code -> stride 80)
    #pragma unroll
    for (int cc = 0; cc < 2; ++cc) {
        for (int i = tid; i < 1024; i += 256) {
            int code = i >> 2, seg = i & 3;
            asm volatile("cp.async.cg.shared.global [%0], [%1], 16;"
                :: "r"(sBsh + cc * 20480 + code * 80 + seg * 16),
                   "l"(cbq + (size_t)(cc * 256 + code) * 64 + seg * 16));
        }
        asm volatile("cp.async.commit_group;");
    }

    // z tile stats
    const int t = tid >> 2, q = tid & 3;
    {
        const float4* zp = (const float4*)(z + (size_t)(tb + t) * 64 + q * 16);
        float ps = 0.f, pa = 0.f, pm = 0.f;
        #pragma unroll
        for (int j = 0; j < 4; ++j) {
            float4 v = zp[j];
            ps = fmaf(v.x, v.x, ps); ps = fmaf(v.y, v.y, ps);
            ps = fmaf(v.z, v.z, ps); ps = fmaf(v.w, v.w, ps);
            pa += fabsf(v.x) + fabsf(v.y) + fabsf(v.z) + fabsf(v.w);
            pm = fmaxf(pm, fmaxf(fmaxf(fabsf(v.x), fabsf(v.y)), fmaxf(fabsf(v.z), fabsf(v.w))));
        }
        psq[tid] = ps; pab[tid] = pa; pmx[tid] = pm;
    }
    if (tid < 128) ((float*)qu)[tid] = g_emaxb[tid];
    if (tid < 64) { ((int*)qu)[128 + tid] = g_s8b[tid]; smn[tid] = 0xFFFFFFFFu; cand[tid] = ~0ULL; }
    if (tid == 0) { qc[0] = 0; qc[1] = 0; }
    for (int i = tid; i < NCODE; i += 256) seq[i] = g_esq[i];
    __syncthreads();

    if (tid < 64) {
        float em = ((float*)qu)[0];
        #pragma unroll
        for (int i = 1; i < 128; ++i) em = fmaxf(em, ((float*)qu)[i]);
        int S8 = ((int*)qu)[128];
        #pragma unroll
        for (int i = 1; i < 64; ++i) S8 = max(S8, ((int*)qu)[128 + i]);
        float zq_ = psq[tid * 4] + psq[tid * 4 + 1] + psq[tid * 4 + 2] + psq[tid * 4 + 3];
        float ab  = pab[tid * 4] + pab[tid * 4 + 1] + pab[tid * 4 + 2] + pab[tid * 4 + 3];
        float mx  = fmaxf(fmaxf(pmx[tid * 4], pmx[tid * 4 + 1]), fmaxf(pmx[tid * 4 + 2], pmx[tid * 4 + 3]));
        float se = em * (1.f / 127.f);
        float zm = fmaxf(mx, 1e-30f);
        float sz = zm * (1.f / 127.f);
        szq[tid] = zq_;
        ssf[tid] = -2.f * se * sz;
        sdl[tid] = se * (ab + sz * (float)S8) + 1e-4f;
        sisz[tid] = 127.f / zm;
    }
    __syncthreads();

    {   // quantize z into smem s8 (stride 80)
        float isz = sisz[t];
        const float4* zp = (const float4*)(z + (size_t)(tb + t) * 64 + q * 16);
        #pragma unroll
        for (int j = 0; j < 4; ++j) {
            float4 v = zp[j];
            int a = __float2int_rn(v.x * isz), b = __float2int_rn(v.y * isz);
            int c = __float2int_rn(v.z * isz), d = __float2int_rn(v.w * isz);
            *(unsigned*)(sA + t * 80 + q * 16 + j * 4) =
                (a & 255) | ((b & 255) << 8) | ((c & 255) << 16) | ((d & 255) << 24);
        }
    }
    asm volatile("cp.async.wait_group 1;");
    __syncthreads();

    // A fragments
    unsigned Ar[4][2][4];
    #pragma unroll
    for (int m = 0; m < 4; ++m)
        #pragma unroll
        for (int kh = 0; kh < 2; ++kh) {
            int base = (m * 16 + gr) * 80 + tig * 4 + kh * 32;
            Ar[m][kh][0] = *(const unsigned*)(sA + base);
            Ar[m][kh][1] = *(const unsigned*)(sA + base + 640);
            Ar[m][kh][2] = *(const unsigned*)(sA + base + 16);
            Ar[m][kh][3] = *(const unsigned*)(sA + base + 656);
        }
    float sf2[4][2];
    #pragma unroll
    for (int m = 0; m < 4; ++m) {
        sf2[m][0] = ssf[m * 16 + gr];
        sf2[m][1] = ssf[m * 16 + gr + 8];
    }
    float minv[8], thrv[8];
    #pragma unroll
    for (int i = 0; i < 8; ++i) { minv[i] = 3.4e38f; thrv[i] = 0.f; }

    auto pass = [&](const signed char* bb, int cb0, bool enq) {
        #pragma unroll
        for (int j = 0; j < 4; ++j) {
            int crow = (w * 32 + j * 8 + gr) * 80 + tig * 4;
            unsigned B0[2], B1[2];
            B0[0] = *(const unsigned*)(bb + crow);
            B0[1] = *(const unsigned*)(bb + crow + 16);
            B1[0] = *(const unsigned*)(bb + crow + 32);
            B1[1] = *(const unsigned*)(bb + crow + 48);
            int col = cb0 + w * 32 + j * 8 + tig * 2;
            float eqA = seq[col], eqB = seq[col + 1];
            int C[4][4];
            #pragma unroll
            for (int m = 0; m < 4; ++m) { C[m][0] = 0; C[m][1] = 0; C[m][2] = 0; C[m][3] = 0; }
            #pragma unroll
            for (int m = 0; m < 4; ++m) imma(C[m], Ar[m][0], B0);
            #pragma unroll
            for (int m = 0; m < 4; ++m) imma(C[m], Ar[m][1], B1);
            #pragma unroll
            for (int m = 0; m < 4; ++m) {
                float s0 = fmaf(sf2[m][0], (float)C[m][0], eqA);
                float s1 = fmaf(sf2[m][0], (float)C[m][1], eqB);
                float s2 = fmaf(sf2[m][1], (float)C[m][2], eqA);
                float s3 = fmaf(sf2[m][1], (float)C[m][3], eqB);
                minv[2 * m]     = fminf(minv[2 * m], fminf(s0, s1));
                minv[2 * m + 1] = fminf(minv[2 * m + 1], fminf(s2, s3));
                if (enq) {
                    int tlo = m * 16 + gr, thi = tlo + 8;
                    if (s0 <= thrv[2 * m]) {
                        unsigned p = atomicAdd(qc, 1u);
                        if (p < QCAP) qu[p] = ((unsigned)tlo << 16) | (unsigned)col; else qc[1] = 1;
                    }
                    if (s1 <= thrv[2 * m]) {
                        unsigned p = atomicAdd(qc, 1u);
                        if (p < QCAP) qu[p] = ((unsigned)tlo << 16) | (unsigned)(col + 1); else qc[1] = 1;
                    }
                    if (s2 <= thrv[2 * m + 1]) {
                        unsigned p = atomicAdd(qc, 1u);
                        if (p < QCAP) qu[p] = ((unsigned)thi << 16) | (unsigned)col; else qc[1] = 1;
                    }
                    if (s3 <= thrv[2 * m + 1]) {
                        unsigned p = atomicAdd(qc, 1u);
                        if (p < QCAP) qu[p] = ((unsigned)thi << 16) | (unsigned)(col + 1); else qc[1] = 1;
                    }
                }
            }
        }
    };
    auto minred = [&]() {
        #pragma unroll
        for (int i = 0; i < 8; ++i) {
            float m = minv[i];
            m = fminf(m, __shfl_xor_sync(~0u, m, 1));
            m = fminf(m, __shfl_xor_sync(~0u, m, 2));
            if (tig == 0) {
                int tt = (i >> 1) * 16 + gr + (i & 1) * 8;
                atomicMin(&smn[tt], fmap(m));
            }
        }
    };

    // pre-pass: chunk 0, min only
    pass(sB, 0, false);
    minred();
    __syncthreads();

    // main passes with live thresholds
    #pragma unroll 1
    for (int c = 0; c < 4; ++c) {
        if (c == 1 || c == 2) asm volatile("cp.async.wait_group 1;");
        if (c == 3)           asm volatile("cp.async.wait_group 0;");
        __syncthreads();
        #pragma unroll
        for (int i = 0; i < 8; ++i) {
            int tt = (i >> 1) * 16 + gr + (i & 1) * 8;
            thrv[i] = unmap(smn[tt]) + sdl[tt];
        }
        pass(sB + (c & 1) * 20480, c * 256, true);
        if (c < 2) {
            minred();
            __syncthreads();
            int src = (c + 2) * 256;
            for (int i = tid; i < 1024; i += 256) {
                int code = i >> 2, seg = i & 3;
                asm volatile("cp.async.cg.shared.global [%0], [%1], 16;"
                    :: "r"(sBsh + (c & 1) * 20480 + code * 80 + seg * 16),
                       "l"(cbq + (size_t)(src + code) * 64 + seg * 16));
            }
            asm volatile("cp.async.commit_group;");
        } else if (c == 2) {
            minred();
            __syncthreads();
        }
    }
    __syncthreads();

    // exact rescore of candidates
    if (!qc[1]) {
        unsigned n = min(qc[0], (unsigned)QCAP);
        for (unsigned i = tid; i < n; i += 256) {
            unsigned e = qu[i];
            int tt = (int)(e >> 16), k = (int)(e & 0xffffu);
            float s = exact_score((const float4*)(z + (size_t)(tb + tt) * 64),
                                  (const float4*)(cb + (size_t)k * 64), szq[tt], seq[k]);
            atomicMin(&cand[tt], packkey(s, k));
        }
    } else {
        int tt = tid >> 2, kb = (tid & 3) * 256;
        unsigned long long best = ~0ULL;
        for (int k = kb; k < kb + 256; ++k) {
            float s = exact_score((const float4*)(z + (size_t)(tb + tt) * 64),
                                  (const float4*)(cb + (size_t)k * 64), szq[tt], seq[k]);
            unsigned long long p = packkey(s, k);
            if (p < best) best = p;
        }
        atomicMin(&cand[tt], best);
    }
    __syncthreads();

    // outputs: index, STE, MSE partial, hist
    {
        int idx = (int)(unsigned)cand[t];
        if (q == 0) {
            out[(size_t)NT * 64 + tb + t] = (float)idx;
            atomicAdd(&g_hist[idx], 1);
        }
        const float4* cp = (const float4*)(cb + (size_t)idx * 64 + q * 16);
        const float4* zp = (const float4*)(z + (size_t)(tb + t) * 64 + q * 16);
        float* op = out + (size_t)(tb + t) * 64 + q * 16;
        double acc = 0.0;
        #pragma unroll
        for (int j = 0; j < 4; ++j) {
            float4 e = cp[j], v = zp[j];
            float dx = e.x - v.x, dy = e.y - v.y, dz = e.z - v.z, dw = e.w - v.w;
            *(float4*)(op + j * 4) = make_float4(v.x + dx, v.y + dy, v.z + dz, v.w + dw);
            acc += (double)(dx * dx) + (double)(dy * dy) + (double)(dz * dz) + (double)(dw * dw);
        }
        srd[tid] = acc;
    }
    __syncthreads();
    #pragma unroll
    for (int o = 128; o; o >>= 1) {
        if (tid < o) srd[tid] += srd[tid + o];
        __syncthreads();
    }
    if (tid == 0) g_partial[blockIdx.x] = srd[0];

    // ---- fused finalization: last block reduces everything ----
    __threadfence();
    __shared__ unsigned lastblk;
    if (tid == 0) lastblk = (atomicAdd(&g_done, 1u) == (unsigned)(NBLK - 1)) ? 1u : 0u;
    __syncthreads();
    if (!lastblk) return;

    double acc = 0.0;
    for (int i = tid; i < NBLK; i += 256) acc += g_partial[i];
    srd[tid] = acc;
    __syncthreads();
    #pragma unroll
    for (int o = 128; o; o >>= 1) {
        if (tid < o) srd[tid] += srd[tid + o];
        __syncthreads();
    }
    double sl = srd[0];
    __syncthreads();

    double ent = 0.0;
    for (int i = tid; i < NCODE; i += 256) {
        float p = (float)g_hist[i] / 131072.0f + 1e-10f;
        ent += (double)(p * logf(p));
    }
    srd[tid] = ent;
    __syncthreads();
    #pragma unroll
    for (int o = 128; o; o >>= 1) {
        if (tid < o) srd[tid] += srd[tid + o];
        __syncthreads();
    }
    if (tid == 0) {
        const size_t b = (size_t)NT * 64 + NT;
        float cl = (float)(sl / (double)((size_t)NT * 64));
        float en = (float)(-srd[0]);
        out[b + 0] = cl;
        out[b + 1] = 0.25f * cl;
        out[b + 2] = -0.1f * (en / 6.9314718055994531f);
        out[b + 3] = expf(en);
        g_done = 0;   // reset for next graph replay
    }
}

extern "C" void kernel_launch(void* const* d_in, const int* in_sizes, int n_in,
                              void* d_out, int out_size)
{
    const float* z  = (const float*)d_in[0];
    const float* cb = (const float*)d_in[1];
    float* out = (float*)d_out;
    static bool done = false;
    if (!done) {
        cudaFuncSetAttribute(vq_main, cudaFuncAttributeMaxDynamicSharedMemorySize, SMEMSZ);
        done = true;
    }
    vq_prep<<<128, 256>>>(cb);
    vq_quant<<<64, 256>>>(cb);
    vq_main<<<NBLK, 256, SMEMSZ>>>(z, cb, out);
}